// round 14
// baseline (speedup 1.0000x reference)
#include <cuda_runtime.h>
#include <cuda_bf16.h>
#include <cstdint>

// ---------------------------------------------------------------------------
// UnifierMnrlLoss, sm_103 legacy-tensor path (bf16 HMMA).
// = R13 + pipelined prologue via cp.async commit-groups:
//   g0 = A/B cols 0-63  -> dim-0 compute starts after only 25.5KB
//   g1 = A/B cols 64-127 (streams behind dim-0 compute)
//   g2 = B chunk-1 prefetch (streams behind dims 0/1)
//   g3 = A chunk-1 reload (overlaps epi(1))
// K-prefix fusion: ONE dim-256 GEMM on raw bf16; prefix dots = accumulator
// snapshots; cosine = acc*invA*invB.
// Symmetry:  kq = qk[:, :2048]^T;  qq,kk symmetric (triangular tiles).
// Tile classes (grid 1568):
//   [0,512):    B  shared qk/kq   dual    [512,784): C qq-tri dual
//   [784,1056): D  kk-tri dual    [1056,1568): A pure qk row-only
// loss = 0.1 + mean log sum exp(s - thr); qq/kk diag auto-mask via threshold.
// Epilogue: packed f32x2 + MUFU ex2.approx; mask fminf(t, -1e30*t).
// ---------------------------------------------------------------------------

#define B_Q   2048
#define K_D   4096
#define L2E   1.4426950408889634f
#define PITCH 136            // 128 + 8 pad (elems): LDSM conflict-free

__device__ __align__(16) __nv_bfloat16 g_Q16[2048 * 256];
__device__ __align__(16) __nv_bfloat16 g_D16[4096 * 256];
__device__ float g_invK[4 * 6144];
__device__ float g_thr[4 * 2048];
__device__ float g_rowsum[4 * 2048];

template <bool E> struct EdgeTag { static constexpr bool value = E; };

// ---------------------------------------------------------------------------
__device__ __forceinline__ void cpa16(uint32_t dst, const void* src) {
    asm volatile("cp.async.cg.shared.global [%0], [%1], 16;\n"
                 :: "r"(dst), "l"(src));
}
__device__ __forceinline__ void cpcommit() {
    asm volatile("cp.async.commit_group;\n" ::: "memory");
}
template <int N>
__device__ __forceinline__ void cpwaitg() {
    asm volatile("cp.async.wait_group %0;\n" :: "n"(N) : "memory");
}
__device__ __forceinline__ void ldsm4(uint32_t* r, uint32_t addr) {
    asm volatile("ldmatrix.sync.aligned.m8n8.x4.shared.b16 {%0,%1,%2,%3}, [%4];"
                 : "=r"(r[0]), "=r"(r[1]), "=r"(r[2]), "=r"(r[3])
                 : "r"(addr));
}
__device__ __forceinline__ void mma_bf16(float* c, const uint32_t* a,
                                         uint32_t b0, uint32_t b1) {
    asm volatile(
        "mma.sync.aligned.m16n8k16.row.col.f32.bf16.bf16.f32 "
        "{%0,%1,%2,%3}, {%4,%5,%6,%7}, {%8,%9}, {%0,%1,%2,%3};"
        : "+f"(c[0]), "+f"(c[1]), "+f"(c[2]), "+f"(c[3])
        : "r"(a[0]), "r"(a[1]), "r"(a[2]), "r"(a[3]), "r"(b0), "r"(b1));
}
__device__ __forceinline__ uint64_t pk2f(float a, float b) {
    uint64_t r;
    asm("mov.b64 %0, {%1, %2};" : "=l"(r) : "f"(a), "f"(b));
    return r;
}
__device__ __forceinline__ void upk2f(uint64_t v, float& a, float& b) {
    asm("mov.b64 {%0, %1}, %2;" : "=f"(a), "=f"(b) : "l"(v));
}
__device__ __forceinline__ uint64_t mul2(uint64_t a, uint64_t b) {
    uint64_t r;
    asm("mul.rn.f32x2 %0, %1, %2;" : "=l"(r) : "l"(a), "l"(b));
    return r;
}
__device__ __forceinline__ uint64_t fma2(uint64_t a, uint64_t b, uint64_t c) {
    uint64_t r;
    asm("fma.rn.f32x2 %0, %1, %2, %3;" : "=l"(r) : "l"(a), "l"(b), "l"(c));
    return r;
}
__device__ __forceinline__ float ex2f(float x) {
    float r;
    asm("ex2.approx.f32 %0, %1;" : "=f"(r) : "f"(x));
    return r;
}

// ---------------------------------------------------------------------------
// prep: zero rowsums + bf16 cast + inverse prefix norms + thresholds.
// Warps [0,2048): paired (q_i, d_i); warps [2048,4096): d rows 2048..4095.
// ---------------------------------------------------------------------------
__global__ void prep3_kernel(const float* __restrict__ q,
                             const float* __restrict__ d) {
    int gt = blockIdx.x * blockDim.x + threadIdx.x;
    if (gt < 4 * 2048) g_rowsum[gt] = 0.0f;
    int warp = gt >> 5;
    int lane = threadIdx.x & 31;
    if (warp >= 4096) return;

    if (warp < 2048) {
        int row = warp;
        const float4* sq4 = (const float4*)(q + (size_t)row * 256) + lane * 2;
        const float4* sd4 = (const float4*)(d + (size_t)row * 256) + lane * 2;
        float4 a0 = sq4[0], a1 = sq4[1];
        float4 b0 = sd4[0], b1 = sd4[1];
        float v[8] = {a0.x, a0.y, a0.z, a0.w, a1.x, a1.y, a1.z, a1.w};
        float u[8] = {b0.x, b0.y, b0.z, b0.w, b1.x, b1.y, b1.z, b1.w};
        float sqq = 0.f, sdd = 0.f, sqd = 0.f;
#pragma unroll
        for (int t = 0; t < 8; t++) {
            sqq = fmaf(v[t], v[t], sqq);
            sdd = fmaf(u[t], u[t], sdd);
            sqd = fmaf(v[t], u[t], sqd);
        }
#pragma unroll
        for (int o = 4; o >= 1; o >>= 1) {
            sqq += __shfl_xor_sync(0xffffffffu, sqq, o);
            sdd += __shfl_xor_sync(0xffffffffu, sdd, o);
            sqd += __shfl_xor_sync(0xffffffffu, sqd, o);
        }
        uint32_t wq[4], wd[4];
#pragma unroll
        for (int t = 0; t < 4; t++) {
            wq[t] = (uint32_t)__bfloat16_as_ushort(__float2bfloat16(v[2 * t])) |
                    ((uint32_t)__bfloat16_as_ushort(__float2bfloat16(v[2 * t + 1])) << 16);
            wd[t] = (uint32_t)__bfloat16_as_ushort(__float2bfloat16(u[2 * t])) |
                    ((uint32_t)__bfloat16_as_ushort(__float2bfloat16(u[2 * t + 1])) << 16);
        }
        uint4 pq; pq.x = wq[0]; pq.y = wq[1]; pq.z = wq[2]; pq.w = wq[3];
        uint4 pd; pd.x = wd[0]; pd.y = wd[1]; pd.z = wd[2]; pd.w = wd[3];
        *(uint4*)(g_Q16 + (size_t)row * 256 + lane * 8) = pq;
        *(uint4*)(g_D16 + (size_t)row * 256 + lane * 8) = pd;

        float q0 = __shfl_sync(0xffffffffu, sqq, 0);
        float q1 = __shfl_sync(0xffffffffu, sqq, 8);
        float q2 = __shfl_sync(0xffffffffu, sqq, 16);
        float q3 = __shfl_sync(0xffffffffu, sqq, 24);
        float e0 = __shfl_sync(0xffffffffu, sdd, 0);
        float e1 = __shfl_sync(0xffffffffu, sdd, 8);
        float e2 = __shfl_sync(0xffffffffu, sdd, 16);
        float e3 = __shfl_sync(0xffffffffu, sdd, 24);
        float x0 = __shfl_sync(0xffffffffu, sqd, 0);
        float x1 = __shfl_sync(0xffffffffu, sqd, 8);
        float x2 = __shfl_sync(0xffffffffu, sqd, 16);
        float x3 = __shfl_sync(0xffffffffu, sqd, 24);
        float qpre[4] = {q0, q0 + q1, q0 + q1 + q2, q0 + q1 + q2 + q3};
        float dpre[4] = {e0, e0 + e1, e0 + e1 + e2, e0 + e1 + e2 + e3};
        float xpre[4] = {x0, x0 + x1, x0 + x1 + x2, x0 + x1 + x2 + x3};
        if (lane < 4) {
            float nq = fmaxf(sqrtf(qpre[lane]), 1e-12f);
            float nd = fmaxf(sqrtf(dpre[lane]), 1e-12f);
            g_thr[lane * 2048 + row] = xpre[lane] / (nq * nd) + 0.1f;
            g_invK[lane * 6144 + 4096 + row] = 1.0f / nq;
            g_invK[lane * 6144 + row] = 1.0f / nd;
        }
    } else {
        int row = warp;          // 2048..4095
        const float4* sd4 = (const float4*)(d + (size_t)row * 256) + lane * 2;
        float4 b0 = sd4[0], b1 = sd4[1];
        float u[8] = {b0.x, b0.y, b0.z, b0.w, b1.x, b1.y, b1.z, b1.w};
        float ss = 0.f;
#pragma unroll
        for (int t = 0; t < 8; t++) ss = fmaf(u[t], u[t], ss);
        ss += __shfl_xor_sync(0xffffffffu, ss, 4);
        ss += __shfl_xor_sync(0xffffffffu, ss, 2);
        ss += __shfl_xor_sync(0xffffffffu, ss, 1);
        float c0 = __shfl_sync(0xffffffffu, ss, 0);
        float c1 = __shfl_sync(0xffffffffu, ss, 8);
        float c2 = __shfl_sync(0xffffffffu, ss, 16);
        float c3 = __shfl_sync(0xffffffffu, ss, 24);
        float pre[4] = {c0, c0 + c1, c0 + c1 + c2, c0 + c1 + c2 + c3};
        uint32_t w[4];
#pragma unroll
        for (int t = 0; t < 4; t++)
            w[t] = (uint32_t)__bfloat16_as_ushort(__float2bfloat16(u[2 * t])) |
                   ((uint32_t)__bfloat16_as_ushort(__float2bfloat16(u[2 * t + 1])) << 16);
        uint4 pk; pk.x = w[0]; pk.y = w[1]; pk.z = w[2]; pk.w = w[3];
        *(uint4*)(g_D16 + (size_t)row * 256 + lane * 8) = pk;
        if (lane < 4)
            g_invK[lane * 6144 + row] =
                1.0f / fmaxf(sqrtf(pre[lane]), 1e-12f);
    }
}

// ---------------------------------------------------------------------------
#define AS_OFF   0          // A:  128 x 136 bf16 = 34816 B (per K-chunk)
#define B0_OFF   34816      // B0:  64 x 136 bf16 = 17408 B (K cols 0..127)
#define B1_OFF   52224      // B1:  64 x 136 bf16 = 17408 B (K cols 128..255)
#define THR_OFF  69632      // rows: -thr*L2E           (4 x 128 floats)
#define IVA_OFF  71680      // rows: invA*L2E           (4 x 128 floats)
#define IVB_OFF  73728      // cols: invB               (4 x 64 floats)
#define THRB_OFF 74752      // cols: -thr*L2E (dual)    (4 x 64 floats)
#define SM_TOTAL 75776

#define NTILES 1568

__global__ __launch_bounds__(256, 3) void score_kernel() {
    extern __shared__ char smem[];
    uint32_t sb = (uint32_t)__cvta_generic_to_shared(smem);
    float* thr_s  = (float*)(smem + THR_OFF);
    float* ivA_s  = (float*)(smem + IVA_OFF);
    float* ivB_s  = (float*)(smem + IVB_OFF);
    float* thrB_s = (float*)(smem + THRB_OFF);

    const int tid = threadIdx.x;
    const int bx = blockIdx.x;

    // ---- tile-class decode ----
    int rt, colOff;
    bool dual, edge = false, tri = false, rowIsD = false, colIsQ = false;
    if (bx < 512) {                       // B: shared qk/kq
        rt = bx >> 5; int ct = bx & 31; colOff = ct * 64;
        dual = true; edge = ((ct >> 1) == rt);
    } else if (bx < 1056) {               // C: qq-tri / D: kk-tri
        bool isC = bx < 784;
        int rem = bx - (isC ? 512 : 784);
        rt = 0;
        while (rem >= 32 - 2 * rt) { rem -= 32 - 2 * rt; rt++; }
        int cto = 2 * rt + rem;
        colOff = cto * 64;
        dual = true; tri = true; edge = (cto <= 2 * rt + 1);
        rowIsD = !isC; colIsQ = isC;
    } else {                              // A: pure qk
        int b = bx - 1056; rt = b >> 5; colOff = 2048 + (b & 31) * 64;
        dual = false;
    }
    const int i0 = rt * 128;
    const __nv_bfloat16* Abase = (rowIsD ? g_D16 : g_Q16) + (size_t)i0 * 256;
    const __nv_bfloat16* Cbase = (colIsQ ? g_Q16 : g_D16) + (size_t)colOff * 256;
    const int ivbKeyBase = colIsQ ? 4096 + colOff : colOff;
    const int rowKeyOff = rowIsD ? i0 : 4096 + i0;

    // quarter loaders: 64 K-columns at a time
    auto loadAh = [&](int chunk, int h) {
        int co = chunk * 128 + h * 64;
        int c8b = h * 8;
#pragma unroll
        for (int idx = tid; idx < 128 * 8; idx += 256) {
            int r = idx >> 3, c8 = (idx & 7) + c8b;
            cpa16(sb + AS_OFF + (uint32_t)(r * PITCH + c8 * 8) * 2,
                  Abase + (size_t)r * 256 + co + ((idx & 7) * 8));
        }
    };
    auto loadBh = [&](int chunk, int h, uint32_t bufOff) {
        int co = chunk * 128 + h * 64;
        int c8b = h * 8;
#pragma unroll
        for (int idx = tid; idx < 64 * 8; idx += 256) {
            int r = idx >> 3, c8 = (idx & 7) + c8b;
            cpa16(sb + bufOff + (uint32_t)(r * PITCH + c8 * 8) * 2,
                  Cbase + (size_t)r * 256 + co + ((idx & 7) * 8));
        }
    };
    auto loadA = [&](int chunk) { loadAh(chunk, 0); loadAh(chunk, 1); };
    auto loadB = [&](int chunk, uint32_t bufOff) {
        loadBh(chunk, 0, bufOff); loadBh(chunk, 1, bufOff);
    };

    // ---- pipelined prologue ----
    loadAh(0, 0); loadBh(0, 0, B0_OFF); cpcommit();   // g0: cols 0-63
    loadAh(0, 1); loadBh(0, 1, B0_OFF); cpcommit();   // g1: cols 64-127
    loadB(1, B1_OFF); cpcommit();                     // g2: B chunk 1
    {
#pragma unroll
        for (int idx = tid; idx < 512; idx += 256) {
            int di = idx >> 7, r = idx & 127;
            thr_s[idx] = -g_thr[di * 2048 + i0 + r] * L2E;
            ivA_s[idx] = g_invK[di * 6144 + rowKeyOff + r] * L2E;
        }
        {
            int di = tid >> 6, c = tid & 63;
            ivB_s[tid] = g_invK[di * 6144 + ivbKeyBase + c];
            if (dual)
                thrB_s[tid] = -g_thr[di * 2048 + colOff + c] * L2E;
        }
    }
    cpwaitg<2>();           // g0 landed (g1, g2 may still be in flight)
    __syncthreads();

    // ---- warp layout ----
    const int wid = tid >> 5, lane = tid & 31;
    const int warpM = wid & 3, warpN = wid >> 2;
    const int m0 = warpM * 32, n0 = warpN * 32;
    const int g = lane >> 2, tig = lane & 3;

    uint32_t aAddr[2], bAddr0[2], bAddr1[2];
    {
        int ra = lane & 15, ka = (lane >> 4) << 3;
#pragma unroll
        for (int mi = 0; mi < 2; mi++)
            aAddr[mi] = sb + AS_OFF +
                ((uint32_t)((m0 + mi * 16 + ra) * PITCH + ka) << 1);
        int rb = (lane & 7) + ((lane >> 4) << 3);
        int kb = ((lane >> 3) & 1) << 3;
#pragma unroll
        for (int p = 0; p < 2; p++) {
            uint32_t rel = ((uint32_t)((n0 + p * 16 + rb) * PITCH + kb) << 1);
            bAddr0[p] = sb + B0_OFF + rel;
            bAddr1[p] = sb + B1_OFF + rel;
        }
    }

    float acc[2][4][4];
#pragma unroll
    for (int mi = 0; mi < 2; mi++)
#pragma unroll
        for (int ni = 0; ni < 4; ni++)
#pragma unroll
            for (int k = 0; k < 4; k++) acc[mi][ni][k] = 0.f;

    const uint64_t nbigp = pk2f(-1e30f, -1e30f);

    auto do_gemm = [&](int kbase, const uint32_t* bAddr) {
#pragma unroll
        for (int k4 = 0; k4 < 4; k4++) {
            const uint32_t koff = (uint32_t)(kbase + k4) * 32;
            uint32_t afr[2][4], bfr[2][4];
#pragma unroll
            for (int mi = 0; mi < 2; mi++) ldsm4(afr[mi], aAddr[mi] + koff);
#pragma unroll
            for (int p = 0; p < 2; p++) ldsm4(bfr[p], bAddr[p] + koff);
#pragma unroll
            for (int mi = 0; mi < 2; mi++)
#pragma unroll
                for (int ni = 0; ni < 4; ni++)
                    mma_bf16(acc[mi][ni], afr[mi],
                             bfr[ni >> 1][(ni & 1) * 2],
                             bfr[ni >> 1][(ni & 1) * 2 + 1]);
        }
    };

    // ---- row-only epilogue (class A) ----
    auto do_epi = [&](int di) {
        uint64_t cbp[4];
#pragma unroll
        for (int ni = 0; ni < 4; ni++)
            cbp[ni] = *(const uint64_t*)&ivB_s[di * 64 + n0 + ni * 8 + tig * 2];
#pragma unroll
        for (int mi = 0; mi < 2; mi++) {
            int il1 = m0 + mi * 16 + g;
            float rf1 = ivA_s[di * 128 + il1];
            float rf2 = ivA_s[di * 128 + il1 + 8];
            float cc1 = thr_s[di * 128 + il1];
            float cc2 = thr_s[di * 128 + il1 + 8];
            uint64_t rfp1 = pk2f(rf1, rf1), ccp1 = pk2f(cc1, cc1);
            uint64_t rfp2 = pk2f(rf2, rf2), ccp2 = pk2f(cc2, cc2);
            float rs1 = 0.f, rs2 = 0.f;
#pragma unroll
            for (int ni = 0; ni < 4; ni++) {
                {
                    uint64_t a2 = pk2f(acc[mi][ni][0], acc[mi][ni][1]);
                    uint64_t u2 = mul2(a2, cbp[ni]);
                    uint64_t t2 = fma2(u2, rfp1, ccp1);
                    uint64_t m2 = mul2(t2, nbigp);
                    float ta, tb, ma, mb;
                    upk2f(t2, ta, tb);
                    upk2f(m2, ma, mb);
                    rs1 += ex2f(fminf(ta, ma));
                    rs1 += ex2f(fminf(tb, mb));
                }
                {
                    uint64_t a2 = pk2f(acc[mi][ni][2], acc[mi][ni][3]);
                    uint64_t u2 = mul2(a2, cbp[ni]);
                    uint64_t t2 = fma2(u2, rfp2, ccp2);
                    uint64_t m2 = mul2(t2, nbigp);
                    float ta, tb, ma, mb;
                    upk2f(t2, ta, tb);
                    upk2f(m2, ma, mb);
                    rs2 += ex2f(fminf(ta, ma));
                    rs2 += ex2f(fminf(tb, mb));
                }
            }
            rs1 += __shfl_xor_sync(0xffffffffu, rs1, 1);
            rs1 += __shfl_xor_sync(0xffffffffu, rs1, 2);
            rs2 += __shfl_xor_sync(0xffffffffu, rs2, 1);
            rs2 += __shfl_xor_sync(0xffffffffu, rs2, 2);
            if (tig == 0) {
                atomicAdd(&g_rowsum[di * 2048 + i0 + il1], rs1);
                atomicAdd(&g_rowsum[di * 2048 + i0 + il1 + 8], rs2);
            }
        }
    };

    // ---- dual epilogue (B/C/D): row + transpose-column ----
    auto do_epi_dual = [&](int di, auto etag) {
        constexpr bool EDGE = decltype(etag)::value;
        uint64_t cbp[4], ccb[4];
#pragma unroll
        for (int ni = 0; ni < 4; ni++) {
            cbp[ni] = *(const uint64_t*)&ivB_s[di * 64 + n0 + ni * 8 + tig * 2];
            ccb[ni] = *(const uint64_t*)&thrB_s[di * 64 + n0 + ni * 8 + tig * 2];
        }
        float cs[8];
#pragma unroll
        for (int k = 0; k < 8; k++) cs[k] = 0.f;
        int jl0 = colOff + n0 + tig * 2;

#pragma unroll
        for (int mi = 0; mi < 2; mi++) {
            int il1 = m0 + mi * 16 + g;
            float rf1 = ivA_s[di * 128 + il1];
            float rf2 = ivA_s[di * 128 + il1 + 8];
            float cc1 = thr_s[di * 128 + il1];
            float cc2 = thr_s[di * 128 + il1 + 8];
            uint64_t rfp1 = pk2f(rf1, rf1), ccp1 = pk2f(cc1, cc1);
            uint64_t rfp2 = pk2f(rf2, rf2), ccp2 = pk2f(cc2, cc2);
            int ig1 = i0 + il1, ig2 = ig1 + 8;
            float rs1 = 0.f, rs2 = 0.f;
#pragma unroll
            for (int ni = 0; ni < 4; ni++) {
                // half 1: rows il1
                {
                    uint64_t a2 = pk2f(acc[mi][ni][0], acc[mi][ni][1]);
                    uint64_t u2 = mul2(a2, cbp[ni]);
                    uint64_t ti2 = fma2(u2, rfp1, ccp1);
                    uint64_t tj2 = fma2(u2, rfp1, ccb[ni]);
                    uint64_t mi2 = mul2(ti2, nbigp);
                    uint64_t mj2 = mul2(tj2, nbigp);
                    float tia, tib, tja, tjb, mia, mib, mja, mjb;
                    upk2f(ti2, tia, tib); upk2f(mi2, mia, mib);
                    upk2f(tj2, tja, tjb); upk2f(mj2, mja, mjb);
                    tia = fminf(tia, mia); tib = fminf(tib, mib);
                    tja = fminf(tja, mja); tjb = fminf(tjb, mjb);
                    if (EDGE) {
                        int da = jl0 + ni * 8 - ig1;
                        int db = da + 1;
                        bool ka = tri ? (da < 0) : (da == 0);
                        bool kb = tri ? (db < 0) : (db == 0);
                        if (tri) {
                            tia = (da < 0) ? -1e30f : tia;
                            tib = (db < 0) ? -1e30f : tib;
                        }
                        tja = ka ? -1e30f : tja;
                        tjb = kb ? -1e30f : tjb;
                    }
                    rs1 += ex2f(tia); rs1 += ex2f(tib);
                    cs[ni * 2]     += ex2f(tja);
                    cs[ni * 2 + 1] += ex2f(tjb);
                }
                // half 2: rows il1+8
                {
                    uint64_t a2 = pk2f(acc[mi][ni][2], acc[mi][ni][3]);
                    uint64_t u2 = mul2(a2, cbp[ni]);
                    uint64_t ti2 = fma2(u2, rfp2, ccp2);
                    uint64_t tj2 = fma2(u2, rfp2, ccb[ni]);
                    uint64_t mi2 = mul2(ti2, nbigp);
                    uint64_t mj2 = mul2(tj2, nbigp);
                    float tia, tib, tja, tjb, mia, mib, mja, mjb;
                    upk2f(ti2, tia, tib); upk2f(mi2, mia, mib);
                    upk2f(tj2, tja, tjb); upk2f(mj2, mja, mjb);
                    tia = fminf(tia, mia); tib = fminf(tib, mib);
                    tja = fminf(tja, mja); tjb = fminf(tjb, mjb);
                    if (EDGE) {
                        int da = jl0 + ni * 8 - ig2;
                        int db = da + 1;
                        bool ka = tri ? (da < 0) : (da == 0);
                        bool kb = tri ? (db < 0) : (db == 0);
                        if (tri) {
                            tia = (da < 0) ? -1e30f : tia;
                            tib = (db < 0) ? -1e30f : tib;
                        }
                        tja = ka ? -1e30f : tja;
                        tjb = kb ? -1e30f : tjb;
                    }
                    rs2 += ex2f(tia); rs2 += ex2f(tib);
                    cs[ni * 2]     += ex2f(tja);
                    cs[ni * 2 + 1] += ex2f(tjb);
                }
            }
            rs1 += __shfl_xor_sync(0xffffffffu, rs1, 1);
            rs1 += __shfl_xor_sync(0xffffffffu, rs1, 2);
            rs2 += __shfl_xor_sync(0xffffffffu, rs2, 1);
            rs2 += __shfl_xor_sync(0xffffffffu, rs2, 2);
            if (tig == 0) {
                atomicAdd(&g_rowsum[di * 2048 + ig1], rs1);
                atomicAdd(&g_rowsum[di * 2048 + ig2], rs2);
            }
        }
#pragma unroll
        for (int k = 0; k < 8; k++) {
            cs[k] += __shfl_xor_sync(0xffffffffu, cs[k], 4);
            cs[k] += __shfl_xor_sync(0xffffffffu, cs[k], 8);
            cs[k] += __shfl_xor_sync(0xffffffffu, cs[k], 16);
        }
        if (lane < 4) {
#pragma unroll
            for (int k = 0; k < 8; k++)
                atomicAdd(&g_rowsum[di * 2048 + colOff + n0 + (k >> 1) * 8 +
                                    lane * 2 + (k & 1)],
                          cs[k]);
        }
    };

    auto epi = [&](int di) {
        if (!dual)      do_epi(di);
        else if (edge)  do_epi_dual(di, EdgeTag<true>{});
        else            do_epi_dual(di, EdgeTag<false>{});
    };

    // ---- main ----
    do_gemm(0, bAddr0);     // dim 0 (cols 0-63; g1/g2 streaming behind)
    epi(0);
    cpwaitg<1>();           // g1 landed (g2 may still be in flight)
    __syncthreads();
    do_gemm(4, bAddr0);     // dim 1 (cols 64-127)
    __syncthreads();        // all warps done reading A chunk0
    loadA(1); cpcommit();   // g3: A chunk1, overlaps epi(1)
    epi(1);
    cpwaitg<0>();           // g2 + g3 landed
    __syncthreads();
    do_gemm(0, bAddr1);     // dim 2 (A chunk1, B1)
    epi(2);
    do_gemm(4, bAddr1);     // dim 3
    epi(3);
}

// ---------------------------------------------------------------------------
__global__ void finalize_kernel(float* out, int n) {
    float local = 0.0f;
    for (int j = threadIdx.x; j < 4 * 2048; j += blockDim.x)
        local += logf(g_rowsum[j]);
    __shared__ float sh[32];
#pragma unroll
    for (int o = 16; o >= 1; o >>= 1)
        local += __shfl_xor_sync(0xffffffffu, local, o);
    if ((threadIdx.x & 31) == 0) sh[threadIdx.x >> 5] = local;
    __syncthreads();
    if (threadIdx.x < 32) {
        float v = (threadIdx.x < (blockDim.x >> 5)) ? sh[threadIdx.x] : 0.0f;
#pragma unroll
        for (int o = 16; o >= 1; o >>= 1)
            v += __shfl_xor_sync(0xffffffffu, v, o);
        if (threadIdx.x == 0) {
            float loss = 0.1f + v / 8192.0f;
            for (int k = 0; k < n; k++) out[k] = loss;
        }
    }
}

// ---------------------------------------------------------------------------
extern "C" void kernel_launch(void* const* d_in, const int* in_sizes, int n_in,
                              void* d_out, int out_size) {
    const float* q = (const float*)d_in[0];
    const float* d = (const float*)d_in[1];
    float* out = (float*)d_out;

    cudaFuncSetAttribute(score_kernel,
                         cudaFuncAttributeMaxDynamicSharedMemorySize, SM_TOTAL);

    prep3_kernel<<<512, 256>>>(q, d);
    score_kernel<<<NTILES, 256, SM_TOTAL>>>();
    finalize_kernel<<<1, 1024>>>(out, out_size);
}